// round 5
// baseline (speedup 1.0000x reference)
#include <cuda_runtime.h>

// EGNN forward, N=50000, E=1.6M, H=32, DX=16, L=2.
// R5: edge kernel processes 2 edges per thread -> smem weight broadcasts
//     amortized 2x (crossbar was the measured 85.6% bottleneck).

#define H    32
#define DX   16
#define NMAX 50048

typedef unsigned long long u64;

__device__ __align__(16) float g_x[NMAX * DX];
__device__ __align__(16) float g_h[NMAX * H];
__device__ __align__(16) float g_A[NMAX * H];
__device__ __align__(16) float g_B[NMAX * H];
__device__ __align__(16) float g_magg[NMAX * H];
__device__ __align__(16) float g_tagg[NMAX * DX];
__device__ float g_cnt[NMAX];
__device__ int g_dummy;

__device__ __forceinline__ float silu_f(float v) {
    return v * (1.0f / (1.0f + __expf(-v)));
}

// ---- f32x2 packed helpers ---------------------------------------------------
__device__ __forceinline__ u64 pack2(float lo, float hi) {
    u64 r; asm("mov.b64 %0, {%1,%2};" : "=l"(r) : "f"(lo), "f"(hi)); return r;
}
__device__ __forceinline__ u64 dup2(float v) {
    u64 r; asm("mov.b64 %0, {%1,%1};" : "=l"(r) : "f"(v)); return r;
}
__device__ __forceinline__ void unpack2(u64 v, float& lo, float& hi) {
    asm("mov.b64 {%0,%1}, %2;" : "=f"(lo), "=f"(hi) : "l"(v));
}
__device__ __forceinline__ void fma2(u64& d, u64 a, u64 b) {
    asm("fma.rn.f32x2 %0, %1, %2, %0;" : "+l"(d) : "l"(a), "l"(b));
}
__device__ __forceinline__ u64 add2(u64 a, u64 b) {
    u64 r; asm("add.rn.f32x2 %0, %1, %2;" : "=l"(r) : "l"(a), "l"(b)); return r;
}

__device__ __forceinline__ void red_add_v4(float* addr, float a, float b, float c, float d) {
    asm volatile("red.global.add.v4.f32 [%0], {%1,%2,%3,%4};"
                 :: "l"(addr), "f"(a), "f"(b), "f"(c), "f"(d)
                 : "memory");
}

// ---------------------------------------------------------------------------
// init
// ---------------------------------------------------------------------------
__global__ __launch_bounds__(128, 4) void init_kernel(
    const float* __restrict__ attrs,
    const float* __restrict__ pos,
    const float* __restrict__ projW,
    const float* __restrict__ embW,
    const float* __restrict__ embB,
    const float* __restrict__ eW1,    // layer0 edge_W1 [32][68]
    const float* __restrict__ eb1,
    int n)
{
    __shared__ __align__(16) float sWa[H][H];
    __shared__ __align__(16) float sWb[H][H];
    for (int idx = threadIdx.x; idx < H * H; idx += 128) {
        int j = idx >> 5, k = idx & 31;
        sWa[k][j] = eW1[j * 68 + k];
        sWb[k][j] = eW1[j * 68 + 32 + k];
    }
    __syncthreads();

    int i = blockIdx.x * 128 + threadIdx.x;
    if (i >= n) return;

    float p0 = pos[i * 3 + 0], p1 = pos[i * 3 + 1], p2 = pos[i * 3 + 2];
    float xv[DX];
#pragma unroll
    for (int j = 0; j < DX; j++)
        xv[j] = projW[j * 3 + 0] * p0 + projW[j * 3 + 1] * p1 + projW[j * 3 + 2] * p2;

    float4* xo = (float4*)&g_x[i * DX];
#pragma unroll
    for (int q = 0; q < 4; q++)
        xo[q] = make_float4(xv[4 * q], xv[4 * q + 1], xv[4 * q + 2], xv[4 * q + 3]);

    float a0 = attrs[i * 3 + 0], a1 = attrs[i * 3 + 1], a2 = attrs[i * 3 + 2];
    float hv[H];
#pragma unroll
    for (int j = 0; j < H; j++)
        hv[j] = embW[j * 3 + 0] * a0 + embW[j * 3 + 1] * a1 + embW[j * 3 + 2] * a2 + embB[j];

    float4* ho = (float4*)&g_h[i * H];
#pragma unroll
    for (int q = 0; q < 8; q++)
        ho[q] = make_float4(hv[4 * q], hv[4 * q + 1], hv[4 * q + 2], hv[4 * q + 3]);

    float Av[H], Bv[H];
#pragma unroll
    for (int j = 0; j < H; j++) { Av[j] = eb1[j]; Bv[j] = 0.0f; }
#pragma unroll
    for (int k = 0; k < H; k++) {
        float hk = hv[k];
        const float4* wa = (const float4*)&sWa[k][0];
        const float4* wb = (const float4*)&sWb[k][0];
#pragma unroll
        for (int q = 0; q < 8; q++) {
            float4 a = wa[q], b = wb[q];
            Av[4 * q + 0] += a.x * hk; Av[4 * q + 1] += a.y * hk;
            Av[4 * q + 2] += a.z * hk; Av[4 * q + 3] += a.w * hk;
            Bv[4 * q + 0] += b.x * hk; Bv[4 * q + 1] += b.y * hk;
            Bv[4 * q + 2] += b.z * hk; Bv[4 * q + 3] += b.w * hk;
        }
    }
    float4* Ao = (float4*)&g_A[i * H];
    float4* Bo = (float4*)&g_B[i * H];
#pragma unroll
    for (int q = 0; q < 8; q++) {
        Ao[q] = make_float4(Av[4 * q], Av[4 * q + 1], Av[4 * q + 2], Av[4 * q + 3]);
        Bo[q] = make_float4(Bv[4 * q], Bv[4 * q + 1], Bv[4 * q + 2], Bv[4 * q + 3]);
    }

    const float4 z4 = make_float4(0.f, 0.f, 0.f, 0.f);
    float4* mz = (float4*)&g_magg[i * H];
    float4* tz = (float4*)&g_tagg[i * DX];
#pragma unroll
    for (int q = 0; q < 8; q++) mz[q] = z4;
#pragma unroll
    for (int q = 0; q < 4; q++) tz[q] = z4;
    g_cnt[i] = 0.0f;
}

// ---------------------------------------------------------------------------
__global__ void count_kernel(const int* __restrict__ ei, int E)
{
    int e = blockIdx.x * blockDim.x + threadIdx.x;
    if (e < E) atomicAdd(&g_cnt[ei[e]], 1.0f);
}

// nop: slot alignment so ncu -s 5 lands on edge_kernel
__global__ void nop_kernel() { if (blockIdx.x == 1u << 30) g_dummy = 1; }

// ---------------------------------------------------------------------------
// edge kernel: T=2 edges per thread; weight broadcasts amortized across both
// ---------------------------------------------------------------------------
#define ETPB 128
#define HQ   (H / 2)

__global__ __launch_bounds__(ETPB) void edge_kernel(
    const int* __restrict__ ei, int E,
    const float* __restrict__ pos,
    const float* __restrict__ W1,   // [32][68], cols 64..67 used
    const float* __restrict__ W2,   // [32][32]
    const float* __restrict__ b2,
    const float* __restrict__ cW1,  // [32][32]
    const float* __restrict__ cb1,
    const float* __restrict__ cW2)  // [32]
{
    __shared__ __align__(16) u64 s_W2t[H][HQ];   // [k][jq] pairs over j
    __shared__ __align__(16) u64 s_cW1t[H][HQ];
    __shared__ u64 s_wr2[HQ];
    __shared__ u64 s_we2[3][HQ];
    __shared__ u64 s_b22[HQ];
    __shared__ u64 s_cb12[HQ];
    __shared__ float s_cw2[H];

    for (int idx = threadIdx.x; idx < H * HQ; idx += ETPB) {
        int k = idx & 31, jq = idx >> 5;
        s_W2t[k][jq]  = pack2(W2[(2 * jq) * H + k],  W2[(2 * jq + 1) * H + k]);
        s_cW1t[k][jq] = pack2(cW1[(2 * jq) * H + k], cW1[(2 * jq + 1) * H + k]);
    }
    if (threadIdx.x < HQ) {
        int jq = threadIdx.x;
        s_wr2[jq]    = pack2(W1[(2 * jq) * 68 + 64], W1[(2 * jq + 1) * 68 + 64]);
        s_we2[0][jq] = pack2(W1[(2 * jq) * 68 + 65], W1[(2 * jq + 1) * 68 + 65]);
        s_we2[1][jq] = pack2(W1[(2 * jq) * 68 + 66], W1[(2 * jq + 1) * 68 + 66]);
        s_we2[2][jq] = pack2(W1[(2 * jq) * 68 + 67], W1[(2 * jq + 1) * 68 + 67]);
        s_b22[jq]    = pack2(b2[2 * jq],  b2[2 * jq + 1]);
        s_cb12[jq]   = pack2(cb1[2 * jq], cb1[2 * jq + 1]);
    }
    if (threadIdx.x < H) s_cw2[threadIdx.x] = cW2[threadIdx.x];
    __syncthreads();

    int e0 = blockIdx.x * (2 * ETPB) + threadIdx.x;
    int e1 = e0 + ETPB;
    if (e0 >= E) return;
    bool v1 = (e1 < E);
    int e1c = v1 ? e1 : e0;

    int row0 = ei[e0],       col0 = ei[E + e0];
    int row1 = ei[e1c],      col1 = ei[E + e1c];

    float ea00 = pos[row0 * 3 + 0] - pos[col0 * 3 + 0];
    float ea01 = pos[row0 * 3 + 1] - pos[col0 * 3 + 1];
    float ea02 = pos[row0 * 3 + 2] - pos[col0 * 3 + 2];
    float ea10 = pos[row1 * 3 + 0] - pos[col1 * 3 + 0];
    float ea11 = pos[row1 * 3 + 1] - pos[col1 * 3 + 1];
    float ea12 = pos[row1 * 3 + 2] - pos[col1 * 3 + 2];

    float cd0[DX], cd1[DX];
    float rad0 = 0.0f, rad1 = 0.0f;
    {
        const float4* xr0 = (const float4*)&g_x[row0 * DX];
        const float4* xc0 = (const float4*)&g_x[col0 * DX];
        const float4* xr1 = (const float4*)&g_x[row1 * DX];
        const float4* xc1 = (const float4*)&g_x[col1 * DX];
#pragma unroll
        for (int q = 0; q < 4; q++) {
            float4 a = xr0[q], b = xc0[q];
            float d0 = a.x - b.x, d1 = a.y - b.y, d2 = a.z - b.z, d3 = a.w - b.w;
            cd0[4 * q + 0] = d0; cd0[4 * q + 1] = d1; cd0[4 * q + 2] = d2; cd0[4 * q + 3] = d3;
            rad0 += d0 * d0 + d1 * d1 + d2 * d2 + d3 * d3;
            float4 c = xr1[q], d = xc1[q];
            float f0 = c.x - d.x, f1 = c.y - d.y, f2 = c.z - d.z, f3 = c.w - d.w;
            cd1[4 * q + 0] = f0; cd1[4 * q + 1] = f1; cd1[4 * q + 2] = f2; cd1[4 * q + 3] = f3;
            rad1 += f0 * f0 + f1 * f1 + f2 * f2 + f3 * f3;
        }
    }

    // ---- layer 1 (A/B factored), both edges ----------------------------
    float acc0[H], acc1[H];
    {
        const ulonglong2* Ar0 = (const ulonglong2*)&g_A[row0 * H];
        const ulonglong2* Bc0 = (const ulonglong2*)&g_B[col0 * H];
        const ulonglong2* Ar1 = (const ulonglong2*)&g_A[row1 * H];
        const ulonglong2* Bc1 = (const ulonglong2*)&g_B[col1 * H];
        u64 a2_0[HQ], a2_1[HQ];
#pragma unroll
        for (int q = 0; q < 8; q++) {
            ulonglong2 a = Ar0[q], b = Bc0[q];
            a2_0[2 * q + 0] = add2(a.x, b.x);
            a2_0[2 * q + 1] = add2(a.y, b.y);
            ulonglong2 c = Ar1[q], d = Bc1[q];
            a2_1[2 * q + 0] = add2(c.x, d.x);
            a2_1[2 * q + 1] = add2(c.y, d.y);
        }
        u64 r20 = dup2(rad0), r21 = dup2(rad1);
        u64 p00 = dup2(ea00), p01 = dup2(ea01), p02 = dup2(ea02);
        u64 p10 = dup2(ea10), p11 = dup2(ea11), p12 = dup2(ea12);
#pragma unroll
        for (int jq = 0; jq < HQ; jq++) {
            u64 wr = s_wr2[jq], w0 = s_we2[0][jq], w1 = s_we2[1][jq], w2 = s_we2[2][jq];
            fma2(a2_0[jq], wr, r20); fma2(a2_1[jq], wr, r21);
            fma2(a2_0[jq], w0, p00); fma2(a2_1[jq], w0, p10);
            fma2(a2_0[jq], w1, p01); fma2(a2_1[jq], w1, p11);
            fma2(a2_0[jq], w2, p02); fma2(a2_1[jq], w2, p12);
        }
#pragma unroll
        for (int jq = 0; jq < HQ; jq++) {
            float lo, hi;
            unpack2(a2_0[jq], lo, hi);
            acc0[2 * jq + 0] = silu_f(lo); acc0[2 * jq + 1] = silu_f(hi);
            unpack2(a2_1[jq], lo, hi);
            acc1[2 * jq + 0] = silu_f(lo); acc1[2 * jq + 1] = silu_f(hi);
        }
    }

    // ---- layer 2, shared weight loads -----------------------------------
    float m0[H], m1[H];
    {
        u64 m2a[HQ], m2b[HQ];
#pragma unroll
        for (int jq = 0; jq < HQ; jq++) { m2a[jq] = s_b22[jq]; m2b[jq] = s_b22[jq]; }
#pragma unroll
        for (int k = 0; k < H; k++) {
            u64 mk0 = dup2(acc0[k]);
            u64 mk1 = dup2(acc1[k]);
            const ulonglong2* w4 = (const ulonglong2*)&s_W2t[k][0];
#pragma unroll
            for (int q = 0; q < 8; q++) {
                ulonglong2 w = w4[q];
                fma2(m2a[2 * q + 0], w.x, mk0);
                fma2(m2a[2 * q + 1], w.y, mk0);
                fma2(m2b[2 * q + 0], w.x, mk1);
                fma2(m2b[2 * q + 1], w.y, mk1);
            }
        }
#pragma unroll
        for (int jq = 0; jq < HQ; jq++) {
            float lo, hi;
            unpack2(m2a[jq], lo, hi);
            m0[2 * jq + 0] = silu_f(lo); m0[2 * jq + 1] = silu_f(hi);
            unpack2(m2b[jq], lo, hi);
            m1[2 * jq + 0] = silu_f(lo); m1[2 * jq + 1] = silu_f(hi);
        }
    }

    // ---- coord head, shared weight loads --------------------------------
    float cm0, cm1;
    {
        u64 c2a[HQ], c2b[HQ];
#pragma unroll
        for (int jq = 0; jq < HQ; jq++) { c2a[jq] = s_cb12[jq]; c2b[jq] = s_cb12[jq]; }
#pragma unroll
        for (int k = 0; k < H; k++) {
            u64 mk0 = dup2(m0[k]);
            u64 mk1 = dup2(m1[k]);
            const ulonglong2* w4 = (const ulonglong2*)&s_cW1t[k][0];
#pragma unroll
            for (int q = 0; q < 8; q++) {
                ulonglong2 w = w4[q];
                fma2(c2a[2 * q + 0], w.x, mk0);
                fma2(c2a[2 * q + 1], w.y, mk0);
                fma2(c2b[2 * q + 0], w.x, mk1);
                fma2(c2b[2 * q + 1], w.y, mk1);
            }
        }
        cm0 = 0.0f; cm1 = 0.0f;
#pragma unroll
        for (int jq = 0; jq < HQ; jq++) {
            float lo, hi;
            unpack2(c2a[jq], lo, hi);
            cm0 += s_cw2[2 * jq + 0] * silu_f(lo);
            cm0 += s_cw2[2 * jq + 1] * silu_f(hi);
            unpack2(c2b[jq], lo, hi);
            cm1 += s_cw2[2 * jq + 0] * silu_f(lo);
            cm1 += s_cw2[2 * jq + 1] * silu_f(hi);
        }
    }

    // ---- scatters --------------------------------------------------------
    {
        float* mago = &g_magg[row0 * H];
#pragma unroll
        for (int q = 0; q < 8; q++)
            red_add_v4(mago + 4 * q, m0[4 * q], m0[4 * q + 1], m0[4 * q + 2], m0[4 * q + 3]);
        float* tago = &g_tagg[row0 * DX];
#pragma unroll
        for (int q = 0; q < 4; q++)
            red_add_v4(tago + 4 * q,
                       cd0[4 * q] * cm0, cd0[4 * q + 1] * cm0,
                       cd0[4 * q + 2] * cm0, cd0[4 * q + 3] * cm0);
    }
    if (v1) {
        float* mago = &g_magg[row1 * H];
#pragma unroll
        for (int q = 0; q < 8; q++)
            red_add_v4(mago + 4 * q, m1[4 * q], m1[4 * q + 1], m1[4 * q + 2], m1[4 * q + 3]);
        float* tago = &g_tagg[row1 * DX];
#pragma unroll
        for (int q = 0; q < 4; q++)
            red_add_v4(tago + 4 * q,
                       cd1[4 * q] * cm1, cd1[4 * q + 1] * cm1,
                       cd1[4 * q + 2] * cm1, cd1[4 * q + 3] * cm1);
    }
}

// ---------------------------------------------------------------------------
// node kernel
// ---------------------------------------------------------------------------
#define NTPB 128

__global__ __launch_bounds__(NTPB, 4) void node_kernel(
    const float* __restrict__ nW1,
    const float* __restrict__ nb1,
    const float* __restrict__ nW2,
    const float* __restrict__ nb2,
    const float* __restrict__ eW1n,
    const float* __restrict__ eb1n,
    const float* __restrict__ linW,
    float* __restrict__ out,
    int n)
{
    __shared__ __align__(16) float sN1t[2 * H][H];
    __shared__ __align__(16) float sN2t[H][H];
    __shared__ __align__(16) float sEAt[H][H];
    __shared__ __align__(16) float sEBt[H][H];

    int i = blockIdx.x * NTPB + threadIdx.x;
    bool active = (i < n);

    float cnt = 0.f;
    float4 xr[4], tr[4], hr[8], mr[8];
    if (active) {
        cnt = g_cnt[i];
        const float4* xp = (const float4*)&g_x[i * DX];
        const float4* tp = (const float4*)&g_tagg[i * DX];
        const float4* hp = (const float4*)&g_h[i * H];
        const float4* mp = (const float4*)&g_magg[i * H];
#pragma unroll
        for (int q = 0; q < 4; q++) { xr[q] = xp[q]; tr[q] = tp[q]; }
#pragma unroll
        for (int q = 0; q < 8; q++) { hr[q] = hp[q]; mr[q] = mp[q]; }
    }

    for (int idx = threadIdx.x; idx < H * 2 * H; idx += NTPB) {
        int j = idx >> 6, k = idx & 63;
        sN1t[k][j] = nW1[idx];
    }
    for (int idx = threadIdx.x; idx < H * H; idx += NTPB) {
        int j = idx >> 5, k = idx & 31;
        sN2t[k][j] = nW2[idx];
        if (eW1n) {
            sEAt[k][j] = eW1n[j * 68 + k];
            sEBt[k][j] = eW1n[j * 68 + 32 + k];
        }
    }
    __syncthreads();

    if (!active) return;

    float inv = 1.0f / fmaxf(cnt, 1.0f);
    const float4 z4 = make_float4(0.f, 0.f, 0.f, 0.f);

    float xv[DX];
#pragma unroll
    for (int q = 0; q < 4; q++) {
        xv[4 * q + 0] = xr[q].x + tr[q].x * inv;
        xv[4 * q + 1] = xr[q].y + tr[q].y * inv;
        xv[4 * q + 2] = xr[q].z + tr[q].z * inv;
        xv[4 * q + 3] = xr[q].w + tr[q].w * inv;
    }
    float4* xp = (float4*)&g_x[i * DX];
    float4* tp = (float4*)&g_tagg[i * DX];
#pragma unroll
    for (int q = 0; q < 4; q++) {
        xp[q] = make_float4(xv[4 * q], xv[4 * q + 1], xv[4 * q + 2], xv[4 * q + 3]);
        tp[q] = z4;
    }

    float hv[H], mg[H];
    float4* mp = (float4*)&g_magg[i * H];
#pragma unroll
    for (int q = 0; q < 8; q++) {
        hv[4 * q + 0] = hr[q].x; hv[4 * q + 1] = hr[q].y;
        hv[4 * q + 2] = hr[q].z; hv[4 * q + 3] = hr[q].w;
        mg[4 * q + 0] = mr[q].x; mg[4 * q + 1] = mr[q].y;
        mg[4 * q + 2] = mr[q].z; mg[4 * q + 3] = mr[q].w;
        mp[q] = z4;
    }

    float u[H];
#pragma unroll
    for (int j = 0; j < H; j++) u[j] = nb1[j];
#pragma unroll
    for (int k = 0; k < H; k++) {
        float v = hv[k];
        const float4* w4 = (const float4*)&sN1t[k][0];
#pragma unroll
        for (int q = 0; q < 8; q++) {
            float4 w = w4[q];
            u[4 * q + 0] += w.x * v; u[4 * q + 1] += w.y * v;
            u[4 * q + 2] += w.z * v; u[4 * q + 3] += w.w * v;
        }
    }
#pragma unroll
    for (int k = 0; k < H; k++) {
        float v = mg[k];
        const float4* w4 = (const float4*)&sN1t[H + k][0];
#pragma unroll
        for (int q = 0; q < 8; q++) {
            float4 w = w4[q];
            u[4 * q + 0] += w.x * v; u[4 * q + 1] += w.y * v;
            u[4 * q + 2] += w.z * v; u[4 * q + 3] += w.w * v;
        }
    }
#pragma unroll
    for (int j = 0; j < H; j++) u[j] = silu_f(u[j]);

    float hn[H];
#pragma unroll
    for (int j = 0; j < H; j++) hn[j] = nb2[j];
#pragma unroll
    for (int k = 0; k < H; k++) {
        float v = u[k];
        const float4* w4 = (const float4*)&sN2t[k][0];
#pragma unroll
        for (int q = 0; q < 8; q++) {
            float4 w = w4[q];
            hn[4 * q + 0] += w.x * v; hn[4 * q + 1] += w.y * v;
            hn[4 * q + 2] += w.z * v; hn[4 * q + 3] += w.w * v;
        }
    }
#pragma unroll
    for (int j = 0; j < H; j++) hn[j] += hv[j];
    float4* hp = (float4*)&g_h[i * H];
#pragma unroll
    for (int q = 0; q < 8; q++)
        hp[q] = make_float4(hn[4 * q], hn[4 * q + 1], hn[4 * q + 2], hn[4 * q + 3]);

    if (eW1n) {
        float Av[H], Bv[H];
#pragma unroll
        for (int j = 0; j < H; j++) { Av[j] = eb1n[j]; Bv[j] = 0.0f; }
#pragma unroll
        for (int k = 0; k < H; k++) {
            float v = hn[k];
            const float4* wa = (const float4*)&sEAt[k][0];
            const float4* wb = (const float4*)&sEBt[k][0];
#pragma unroll
            for (int q = 0; q < 8; q++) {
                float4 a = wa[q], b = wb[q];
                Av[4 * q + 0] += a.x * v; Av[4 * q + 1] += a.y * v;
                Av[4 * q + 2] += a.z * v; Av[4 * q + 3] += a.w * v;
                Bv[4 * q + 0] += b.x * v; Bv[4 * q + 1] += b.y * v;
                Bv[4 * q + 2] += b.z * v; Bv[4 * q + 3] += b.w * v;
            }
        }
        float4* Ao = (float4*)&g_A[i * H];
        float4* Bo = (float4*)&g_B[i * H];
#pragma unroll
        for (int q = 0; q < 8; q++) {
            Ao[q] = make_float4(Av[4 * q], Av[4 * q + 1], Av[4 * q + 2], Av[4 * q + 3]);
            Bo[q] = make_float4(Bv[4 * q], Bv[4 * q + 1], Bv[4 * q + 2], Bv[4 * q + 3]);
        }
    }

    if (linW) {
#pragma unroll
        for (int c = 0; c < 3; c++) {
            float acc = 0.0f;
#pragma unroll
            for (int k = 0; k < DX; k++) acc += linW[c * DX + k] * xv[k];
            out[i * 3 + c] = acc;
        }
    }
}

// ---------------------------------------------------------------------------
extern "C" void kernel_launch(void* const* d_in, const int* in_sizes, int n_in,
                              void* d_out, int out_size)
{
    const float* node_attrs = (const float*)d_in[0];
    const float* positions  = (const float*)d_in[1];
    const int*   edge_index = (const int*)  d_in[2];
    const float* proj_W     = (const float*)d_in[3];
    const float* emb_in_W   = (const float*)d_in[4];
    const float* emb_in_b   = (const float*)d_in[5];
    const float* edge_W1    = (const float*)d_in[6];
    const float* edge_b1    = (const float*)d_in[7];
    const float* edge_W2    = (const float*)d_in[8];
    const float* edge_b2    = (const float*)d_in[9];
    const float* node_W1    = (const float*)d_in[10];
    const float* node_b1    = (const float*)d_in[11];
    const float* node_W2    = (const float*)d_in[12];
    const float* node_b2    = (const float*)d_in[13];
    const float* coord_W1   = (const float*)d_in[14];
    const float* coord_b1   = (const float*)d_in[15];
    const float* coord_W2   = (const float*)d_in[16];
    const float* lin_W      = (const float*)d_in[19];

    int n = in_sizes[0] / 3;
    int E = in_sizes[2] / 2;

    float* out = (float*)d_out;

    init_kernel<<<(n + 127) / 128, 128>>>(node_attrs, positions, proj_W,
                                          emb_in_W, emb_in_b,
                                          edge_W1, edge_b1, n);
    count_kernel<<<(E + 255) / 256, 256>>>(edge_index, E);
    nop_kernel<<<1, 32>>>();

    int eblocks = (E + 2 * ETPB - 1) / (2 * ETPB);
    for (int l = 0; l < 2; l++) {
        edge_kernel<<<eblocks, ETPB>>>(
            edge_index, E, positions,
            edge_W1 + l * H * 68,
            edge_W2 + l * H * H, edge_b2 + l * H,
            coord_W1 + l * H * H, coord_b1 + l * H,
            coord_W2 + l * H);

        node_kernel<<<(n + NTPB - 1) / NTPB, NTPB>>>(
            node_W1 + l * H * 2 * H, node_b1 + l * H,
            node_W2 + l * H * H,     node_b2 + l * H,
            (l == 0) ? edge_W1 + H * 68 : nullptr,
            (l == 0) ? edge_b1 + H      : nullptr,
            (l == 1) ? lin_W            : nullptr,
            out, n);
    }
}